// round 13
// baseline (speedup 1.0000x reference)
#include <cuda_runtime.h>
#include <cuda_fp16.h>
#include <cstdint>

// Problem constants
#define IN_F   2048
#define OUT_F  2048
#define NROWS  8192
#define INV_SQRT_D 0.022097086912079610f

// Tiling
#define BM 128
#define BN 128
#define KB 128                      // K halfs per stage (two 16KB sub-tiles)
#define NSTG (IN_F / KB)            // 16 stages per tile
#define TILE_HALFS 8192             // 128 rows * 64 halfs (one k-sub-tile)
#define SUB_BYTES 16384
#define STAGE_BYTES 98304           // A(32K) + Bk(32K) + Bm(32K)
#define NBUF 2
#define SMEM_TOTAL (NBUF * STAGE_BYTES)   // 196608
#define MU_BASE ((size_t)OUT_F * IN_F)
#define NTHREADS 256
#define NSM 148
#define NTILES ((NROWS / BM) * (OUT_F / BN))   // 64 * 16 = 1024

// Scratch globals: TILED + SWIZZLED layouts (see prep); 32 k-sub-tiles/block
__device__ __align__(1024) __half Xh[(size_t)NROWS * IN_F];
__device__ __align__(1024) __half Wh[2 * (size_t)OUT_F * IN_F];  // [keys tiles ; mu tiles]

// ---------------------------------------------------------------------------
// PTX helpers
// ---------------------------------------------------------------------------
__device__ __forceinline__ void ldmatrix_x4(uint32_t* r, uint32_t addr) {
    asm volatile("ldmatrix.sync.aligned.m8n8.x4.shared.b16 {%0,%1,%2,%3}, [%4];\n"
                 : "=r"(r[0]), "=r"(r[1]), "=r"(r[2]), "=r"(r[3]) : "r"(addr));
}

__device__ __forceinline__ void mma16816(float* c, const uint32_t* a, const uint32_t* b) {
    asm volatile(
        "mma.sync.aligned.m16n8k16.row.col.f32.f16.f16.f32 "
        "{%0,%1,%2,%3}, {%4,%5,%6,%7}, {%8,%9}, {%0,%1,%2,%3};\n"
        : "+f"(c[0]), "+f"(c[1]), "+f"(c[2]), "+f"(c[3])
        : "r"(a[0]), "r"(a[1]), "r"(a[2]), "r"(a[3]), "r"(b[0]), "r"(b[1]));
}

__device__ __forceinline__ void mbar_init(uint32_t addr, uint32_t count) {
    asm volatile("mbarrier.init.shared.b64 [%0], %1;" :: "r"(addr), "r"(count) : "memory");
}
__device__ __forceinline__ void mbar_expect_tx(uint32_t addr, uint32_t bytes) {
    asm volatile("mbarrier.arrive.expect_tx.shared.b64 _, [%0], %1;"
                 :: "r"(addr), "r"(bytes) : "memory");
}
__device__ __forceinline__ void mbar_arrive(uint32_t addr) {
    asm volatile("mbarrier.arrive.shared.b64 _, [%0];" :: "r"(addr) : "memory");
}
__device__ __forceinline__ void mbar_wait(uint32_t addr, uint32_t parity) {
    asm volatile(
        "{\n\t.reg .pred P;\n\t"
        "WL_%=:\n\t"
        "mbarrier.try_wait.parity.shared.b64 P, [%0], %1, 0x989680;\n\t"
        "@!P bra WL_%=;\n\t}"
        :: "r"(addr), "r"(parity) : "memory");
}
__device__ __forceinline__ void bulk_g2s(uint32_t dst, const void* src,
                                         uint32_t bytes, uint32_t mbar) {
    asm volatile(
        "cp.async.bulk.shared::cluster.global.mbarrier::complete_tx::bytes [%0], [%1], %2, [%3];"
        :: "r"(dst), "l"(src), "r"(bytes), "r"(mbar) : "memory");
}

// ---------------------------------------------------------------------------
// Prep v2: 16 elements/thread, one address computation per thread.
// Layout: block(row>>7), sub-tile(k8>>3): base = (blk*32+kst)*8192 + rloc*64,
//         chunk c (0..7): half-offset base + ((c ^ (rloc&7)) * 8).
// ---------------------------------------------------------------------------
#define XBLOCKS2 ((unsigned)((size_t)NROWS * IN_F / 16 / 256))    // 4096
#define WBLOCKS2 ((unsigned)(OUT_F * IN_F / 16 / 256))            // 1024

__device__ __forceinline__ uint4 pack8(float4 a, float4 b) {
    __half2 h0 = __floats2half2_rn(a.x, a.y);
    __half2 h1 = __floats2half2_rn(a.z, a.w);
    __half2 h2 = __floats2half2_rn(b.x, b.y);
    __half2 h3 = __floats2half2_rn(b.z, b.w);
    uint4 p;
    p.x = *(uint32_t*)&h0; p.y = *(uint32_t*)&h1;
    p.z = *(uint32_t*)&h2; p.w = *(uint32_t*)&h3;
    return p;
}

__global__ void prep_all(const float* __restrict__ x,
                         const float* __restrict__ mu,
                         const float* __restrict__ sigma) {
    if (blockIdx.x < XBLOCKS2) {
        size_t q = (size_t)blockIdx.x * 256 + threadIdx.x;
        size_t i = q * 16;                       // 16 consecutive elems, one row
        int row  = (int)(i >> 11);
        int k8   = (int)((i & 2047) >> 3);       // even chunk index
        int rloc = row & 127;
        size_t base = ((size_t)((row >> 7) * 32 + (k8 >> 3))) * TILE_HALFS + rloc * 64;
        int c0 = k8 & 7;
        size_t d0 = base + ((c0       ^ (rloc & 7)) * 8);
        size_t d1 = base + (((c0 + 1) ^ (rloc & 7)) * 8);

        const float4* xs = (const float4*)(x + i);
        float4 a0 = xs[0], a1 = xs[1], a2 = xs[2], a3 = xs[3];
        *(uint4*)(Xh + d0) = pack8(a0, a1);
        *(uint4*)(Xh + d1) = pack8(a2, a3);
    } else {
        size_t q = (size_t)(blockIdx.x - XBLOCKS2) * 256 + threadIdx.x;
        size_t i = q * 16;
        int row  = (int)(i >> 11);
        int k8   = (int)((i & 2047) >> 3);
        int rloc = row & 127;
        size_t base = ((size_t)((row >> 7) * 32 + (k8 >> 3))) * TILE_HALFS + rloc * 64;
        int c0 = k8 & 7;
        size_t d0 = base + ((c0       ^ (rloc & 7)) * 8);
        size_t d1 = base + (((c0 + 1) ^ (rloc & 7)) * 8);

        const float4* ms = (const float4*)(mu + i);
        const float4* ss = (const float4*)(sigma + i);
        float mf[16], sf[16];
        #pragma unroll
        for (int v = 0; v < 4; v++) {
            float4 m4 = ms[v], s4 = ss[v];
            mf[v*4+0]=m4.x; mf[v*4+1]=m4.y; mf[v*4+2]=m4.z; mf[v*4+3]=m4.w;
            sf[v*4+0]=s4.x; sf[v*4+1]=s4.y; sf[v*4+2]=s4.z; sf[v*4+3]=s4.w;
        }
        __half kh[16], mh[16];
        #pragma unroll
        for (int j = 0; j < 16; j++) {
            float s  = sf[j];
            float sp = (s > 15.f) ? s : __logf(1.f + __expf(s));
            kh[j] = __float2half_rn(mf[j] * sp);
            mh[j] = __float2half_rn(mf[j]);
        }
        *(uint4*)(Wh + d0)           = ((uint4*)kh)[0];
        *(uint4*)(Wh + d1)           = ((uint4*)kh)[1];
        *(uint4*)(Wh + MU_BASE + d0) = ((uint4*)mh)[0];
        *(uint4*)(Wh + MU_BASE + d1) = ((uint4*)mh)[1];
    }
}

// ---------------------------------------------------------------------------
// Persistent fused GEMM: 148 CTAs, ring-2 of 96KB stages; hoisted next-stage
// wait + early release + anti-phased ks order (R12 champion, unchanged).
// ---------------------------------------------------------------------------
__device__ __forceinline__ void issue_gs(uint32_t smem_u32, uint32_t mbarF_u32,
                                         int gs, int cta) {
    const int tile = cta + (gs >> 4) * NSM;
    const int s    = gs & 15;
    const int mblk = tile >> 4;
    const int nblk = tile & 15;
    const __half* gA  = Xh + ((size_t)mblk * 32 + 2 * s) * TILE_HALFS;
    const __half* gBk = Wh + ((size_t)nblk * 32 + 2 * s) * TILE_HALFS;
    const __half* gBm = gBk + MU_BASE;

    const int b = gs & 1;
    const uint32_t mb  = mbarF_u32 + b * 8;
    const uint32_t dst = smem_u32 + b * STAGE_BYTES;
    mbar_expect_tx(mb, STAGE_BYTES);
    bulk_g2s(dst,         gA,  2 * SUB_BYTES, mb);
    bulk_g2s(dst + 32768, gBk, 2 * SUB_BYTES, mb);
    bulk_g2s(dst + 65536, gBm, 2 * SUB_BYTES, mb);
}

__global__ __launch_bounds__(NTHREADS, 1) void gemm_fused(
    const float* __restrict__ gate,
    float* __restrict__ outFinal,
    float* __restrict__ outScores,
    float* __restrict__ outMasked)
{
    extern __shared__ char smem[];
    __shared__ __align__(8) uint64_t mbarF[NBUF];
    __shared__ __align__(8) uint64_t mbarE[NBUF];

    const uint32_t smem_u32  = (uint32_t)__cvta_generic_to_shared(smem);
    const uint32_t mbarF_u32 = (uint32_t)__cvta_generic_to_shared(mbarF);
    const uint32_t mbarE_u32 = (uint32_t)__cvta_generic_to_shared(mbarE);

    const int tid    = threadIdx.x;
    const int lane   = tid & 31;
    const int wid    = tid >> 5;
    const int warp_m = wid >> 2;      // 0..1 -> 64 rows each; also SMSP-pair phase
    const int warp_n = wid & 3;       // 0..3 -> 32 cols each
    const int cta    = blockIdx.x;

    const int ks_off = warp_m * 4;    // anti-phase the two warps per SMSP

    const int my_tiles = (NTILES - 1 - cta) / NSM + 1;
    const int total_gs = my_tiles * NSTG;

    if (tid == 0) {
        #pragma unroll
        for (int b = 0; b < NBUF; b++) {
            mbar_init(mbarF_u32 + b * 8, 1);
            mbar_init(mbarE_u32 + b * 8, 8);   // one arrive per warp
        }
    }
    __syncthreads();

    if (tid == 0) {
        issue_gs(smem_u32, mbarF_u32, 0, cta);
        issue_gs(smem_u32, mbarF_u32, 1, cta);
    }

    float acck[4][4][4], accm[4][4][4];
    #pragma unroll
    for (int mt = 0; mt < 4; mt++)
        #pragma unroll
        for (int nt = 0; nt < 4; nt++)
            #pragma unroll
            for (int q = 0; q < 4; q++) { acck[mt][nt][q] = 0.f; accm[mt][nt][q] = 0.f; }

    const int a_row = lane & 15;
    const int a_sel = lane >> 4;
    const int b_row = (lane & 7) + ((lane & 16) >> 1);
    const int b_sel = (lane & 8) ? 1 : 0;

    // Wait for stage 0 once; subsequent waits are hoisted into MMA shadows.
    mbar_wait(mbarF_u32, 0);

    for (int gs = 0; gs < total_gs; gs++) {
        const int b = gs & 1;

        const uint32_t sA  = smem_u32 + b * STAGE_BYTES;
        const uint32_t sBk = sA + 32768;
        const uint32_t sBm = sA + 65536;

        #pragma unroll
        for (int ksi = 0; ksi < 8; ksi++) {
            const int ks  = (ksi + ks_off) & 7;   // anti-phased traversal
            const int sub = (ks >> 2) * SUB_BYTES;
            const int kk  = ks & 3;
            uint32_t af[4][4];
            #pragma unroll
            for (int mt = 0; mt < 4; mt++) {
                int row = warp_m * 64 + mt * 16 + a_row;
                int ch  = (kk * 2 + a_sel) ^ (row & 7);
                ldmatrix_x4(af[mt], sA + sub + row * 128 + ch * 16);
            }
            uint32_t bk[4][2], bmu[4][2];
            #pragma unroll
            for (int bt = 0; bt < 2; bt++) {
                int row = warp_n * 32 + bt * 16 + b_row;
                int ch  = (kk * 2 + b_sel) ^ (row & 7);
                uint32_t r[4];
                ldmatrix_x4(r, sBk + sub + row * 128 + ch * 16);
                bk[2*bt  ][0] = r[0]; bk[2*bt  ][1] = r[1];
                bk[2*bt+1][0] = r[2]; bk[2*bt+1][1] = r[3];
                uint32_t t[4];
                ldmatrix_x4(t, sBm + sub + row * 128 + ch * 16);
                bmu[2*bt  ][0] = t[0]; bmu[2*bt  ][1] = t[1];
                bmu[2*bt+1][0] = t[2]; bmu[2*bt+1][1] = t[3];
            }

            if (ksi == 7) {
                // Early release: all smem reads of this stage are issued.
                if (lane == 0) mbar_arrive(mbarE_u32 + b * 8);
                // Hoisted wait for next stage: overlaps the final MMA batch.
                if (gs + 1 < total_gs) {
                    const int n = gs + 1;
                    mbar_wait(mbarF_u32 + (n & 1) * 8, (n >> 1) & 1);
                }
            }

            #pragma unroll
            for (int mt = 0; mt < 4; mt++) {
                #pragma unroll
                for (int nt = 0; nt < 4; nt++) {
                    mma16816(acck[mt][nt], af[mt], bk[nt]);
                    mma16816(accm[mt][nt], af[mt], bmu[nt]);
                }
            }
        }

        // Producer: refill buffer b with global stage gs+2 (may be next tile).
        if (tid == 0 && gs + 2 < total_gs) {
            const int t = gs + 2;
            mbar_wait(mbarE_u32 + b * 8, (((t >> 1) & 1) ^ 1));
            issue_gs(smem_u32, mbarF_u32, t, cta);
        }

        // Tile finished: fused epilogue (overlaps next tile's loads).
        if ((gs & 15) == 15) {
            const int tile = cta + (gs >> 4) * NSM;
            const int bm = (tile >> 4) * BM;
            const int bn = (tile & 15) * BN;

            #pragma unroll
            for (int mt = 0; mt < 4; mt++) {
                int r0 = bm + warp_m * 64 + mt * 16 + (lane >> 2);
                #pragma unroll
                for (int nt = 0; nt < 4; nt++) {
                    int c = bn + warp_n * 32 + nt * 8 + (lane & 3) * 2;
                    float2 g = __ldg((const float2*)(gate + c));

                    float s0 = acck[mt][nt][0] * INV_SQRT_D;
                    float s1 = acck[mt][nt][1] * INV_SQRT_D;
                    float m0 = accm[mt][nt][0] * fmaxf(s0 - g.x, 0.f);
                    float m1 = accm[mt][nt][1] * fmaxf(s1 - g.y, 0.f);
                    size_t o0 = (size_t)r0 * OUT_F + c;
                    *(float2*)(outScores + o0) = make_float2(s0, s1);
                    *(float2*)(outFinal  + o0) = make_float2(m0, m1);
                    *(float2*)(outMasked + o0) = make_float2(m0, m1);

                    float s2 = acck[mt][nt][2] * INV_SQRT_D;
                    float s3 = acck[mt][nt][3] * INV_SQRT_D;
                    float m2 = accm[mt][nt][2] * fmaxf(s2 - g.x, 0.f);
                    float m3 = accm[mt][nt][3] * fmaxf(s3 - g.y, 0.f);
                    size_t o1 = (size_t)(r0 + 8) * OUT_F + c;
                    *(float2*)(outScores + o1) = make_float2(s2, s3);
                    *(float2*)(outFinal  + o1) = make_float2(m2, m3);
                    *(float2*)(outMasked + o1) = make_float2(m2, m3);

                    #pragma unroll
                    for (int q = 0; q < 4; q++) { acck[mt][nt][q] = 0.f; accm[mt][nt][q] = 0.f; }
                }
            }
        }
    }
}

// ---------------------------------------------------------------------------
// Launch
// ---------------------------------------------------------------------------
extern "C" void kernel_launch(void* const* d_in, const int* in_sizes, int n_in,
                              void* d_out, int out_size) {
    const float* x     = (const float*)d_in[0];
    const float* mu    = (const float*)d_in[1];
    const float* sigma = (const float*)d_in[2];
    const float* gate  = (const float*)d_in[3];

    float* out  = (float*)d_out;
    float* out0 = out;                               // final_output
    float* out1 = out + (size_t)NROWS * OUT_F;       // scores
    float* out2 = out + 2 * (size_t)NROWS * OUT_F;   // masked_output

    prep_all<<<XBLOCKS2 + WBLOCKS2, 256>>>(x, mu, sigma);

    cudaFuncSetAttribute(gemm_fused, cudaFuncAttributeMaxDynamicSharedMemorySize, SMEM_TOTAL);
    gemm_fused<<<NSM, NTHREADS, SMEM_TOTAL>>>(gate, out0, out1, out2);
}